// round 16
// baseline (speedup 1.0000x reference)
#include <cuda_runtime.h>
#include <cuda_bf16.h>
#include <cstdint>
#include <math.h>

#define SEQ  2048
#define EMB  2048
#define NH   16
#define HD   128

// ---------------- scratch (allocation-free: static device globals) ----------------
__device__ __nv_bfloat16 g_hsh[(size_t)SEQ * EMB];
__device__ __nv_bfloat16 g_hsl[(size_t)SEQ * EMB];
__device__ __nv_bfloat16 g_wqh[(size_t)EMB * EMB];
__device__ __nv_bfloat16 g_wql[(size_t)EMB * EMB];
__device__ __nv_bfloat16 g_wkh[(size_t)EMB * EMB];
__device__ __nv_bfloat16 g_wkl[(size_t)EMB * EMB];
__device__ __nv_bfloat16 g_wvh[(size_t)EMB * EMB];
__device__ __nv_bfloat16 g_wvl[(size_t)EMB * EMB];
__device__ __nv_bfloat16 g_woh[(size_t)EMB * EMB];
__device__ __nv_bfloat16 g_wol[(size_t)EMB * EMB];
__device__ __nv_bfloat16 g_qh[(size_t)SEQ * EMB];
__device__ __nv_bfloat16 g_ql[(size_t)SEQ * EMB];
__device__ __nv_bfloat16 g_kh[(size_t)SEQ * EMB];
__device__ __nv_bfloat16 g_kl[(size_t)SEQ * EMB];
__device__ __nv_bfloat16 g_vth[(size_t)EMB * SEQ];
__device__ __nv_bfloat16 g_vtl[(size_t)EMB * SEQ];
__device__ __nv_bfloat16 g_ctxh[(size_t)SEQ * EMB];
__device__ __nv_bfloat16 g_ctxl[(size_t)SEQ * EMB];

// ======================= helpers ==============
__device__ __forceinline__ uint32_t smem_u32(const void* p) {
    uint32_t a;
    asm("{ .reg .u64 t; cvta.to.shared.u64 t, %1; cvt.u32.u64 %0, t; }" : "=r"(a) : "l"(p));
    return a;
}
#define LDSM4(r0, r1, r2, r3, addr)                                               \
    asm volatile("ldmatrix.sync.aligned.m8n8.x4.shared.b16 {%0,%1,%2,%3}, [%4];"  \
        : "=r"(r0), "=r"(r1), "=r"(r2), "=r"(r3) : "r"(addr))
#define MMA_BF16(c, a, b0, b1)                                                    \
    asm volatile("mma.sync.aligned.m16n8k16.row.col.f32.bf16.bf16.f32 "           \
        "{%0,%1,%2,%3}, {%4,%5,%6,%7}, {%8,%9}, {%0,%1,%2,%3};"                   \
        : "+f"((c)[0]), "+f"((c)[1]), "+f"((c)[2]), "+f"((c)[3])                  \
        : "r"((a)[0]), "r"((a)[1]), "r"((a)[2]), "r"((a)[3]), "r"(b0), "r"(b1))
#define CP16(dst, src) \
    asm volatile("cp.async.cg.shared.global [%0], [%1], 16;" :: "r"(dst), "l"(src))
#define CP_COMMIT() asm volatile("cp.async.commit_group;")
#define CP_WAIT(n)  asm volatile("cp.async.wait_group %0;" :: "n"(n))

__device__ __forceinline__ void split_bf16(float x, __nv_bfloat16& h, __nv_bfloat16& l) {
    h = __float2bfloat16(x);
    l = __float2bfloat16(x - __bfloat162float(h));
}
__device__ __forceinline__ uint32_t pack_bf2(__nv_bfloat16 a, __nv_bfloat16 b) {
    __nv_bfloat162 p = __halves2bfloat162(a, b);
    return *(uint32_t*)&p;
}

// ---------------- input split: fp32 -> bf16 hi/lo ----------------
__global__ void __launch_bounds__(256) split_one(
    const float4* __restrict__ src, uint2* __restrict__ dh, uint2* __restrict__ dl)
{
    const int i = blockIdx.x * 256 + threadIdx.x;
    float4 x = src[i];
    __nv_bfloat16 h0, h1, h2, h3, l0, l1, l2, l3;
    split_bf16(x.x, h0, l0); split_bf16(x.y, h1, l1);
    split_bf16(x.z, h2, l2); split_bf16(x.w, h3, l3);
    dh[i] = make_uint2(pack_bf2(h0, h1), pack_bf2(h2, h3));
    dl[i] = make_uint2(pack_bf2(l0, l1), pack_bf2(l2, l3));
}

// ============ HMMA NT GEMM (R15-proven) + fused RoPE/transpose epilogue ========
// 512 threads, 16 warps, warp tile 32x32, double-buffered smem, bf16 inputs.
// mode 0: RoPE+scale -> qh/ql   mode 1: RoPE -> kh/kl
// mode 2: transpose -> vth/vtl  mode 3: fp32 -> Cout
#define KC      32
#define NCHUNK  (EMB / KC)
#define RSTRIDE 40
#define BUF_E   (128 * RSTRIDE)
#define STAGE_E (4 * BUF_E)
#define GSM_BYTES (2 * STAGE_E * 2)     // 81920 >= 128*129*4 = 66048 epilogue tile

__global__ void __launch_bounds__(512, 1) gemm_fused(
    const __nv_bfloat16* __restrict__ Ah_, const __nv_bfloat16* __restrict__ Al_,
    const __nv_bfloat16* __restrict__ Bh0, const __nv_bfloat16* __restrict__ Bl0,
    const __nv_bfloat16* __restrict__ Bh1, const __nv_bfloat16* __restrict__ Bl1,
    const __nv_bfloat16* __restrict__ Bh2, const __nv_bfloat16* __restrict__ Bl2,
    __nv_bfloat16* __restrict__ qh, __nv_bfloat16* __restrict__ ql,
    __nv_bfloat16* __restrict__ kh, __nv_bfloat16* __restrict__ kl,
    __nv_bfloat16* __restrict__ vth, __nv_bfloat16* __restrict__ vtl,
    float* __restrict__ Cout, int mode_base)
{
    const int mode = (mode_base >= 0) ? mode_base : (int)blockIdx.z;
    const __nv_bfloat16* Bh = (mode == 1) ? Bh1 : (mode == 2) ? Bh2 : Bh0;
    const __nv_bfloat16* Bl = (mode == 1) ? Bl1 : (mode == 2) ? Bl2 : Bl0;

    extern __shared__ __align__(16) __nv_bfloat16 sm[];

    const int t    = threadIdx.x;
    const int lane = t & 31;
    const int wid  = t >> 5;           // 0..15
    const int wm   = wid & 3;          // 32-row band
    const int wn   = wid >> 2;         // 0..3: 32-col band
    const int m0   = blockIdx.y * 128;
    const int n0   = blockIdx.x * 128;
    const int id   = lane >> 3;
    const int r8   = lane & 7;

    float acc[2][4][4];
#pragma unroll
    for (int i = 0; i < 2; i++)
#pragma unroll
        for (int j = 0; j < 4; j++)
#pragma unroll
            for (int c = 0; c < 4; c++) acc[i][j][c] = 0.0f;

    // per-thread load slot: row = t>>2 (0..127), 8-elem group cq = (t&3)*8.
    const int prow = t >> 2;
    const int pcq  = (t & 3) * 8;
    const __nv_bfloat16* gsrc[4] = {
        Ah_ + (size_t)(m0 + prow) * EMB + pcq,
        Al_ + (size_t)(m0 + prow) * EMB + pcq,
        Bh  + (size_t)(n0 + prow) * EMB + pcq,
        Bl  + (size_t)(n0 + prow) * EMB + pcq
    };
    const int soff = prow * RSTRIDE + pcq;

    uint4 pref[4];

    auto LOADG = [&](int k0) {
#pragma unroll
        for (int j = 0; j < 4; j++)
            pref[j] = *(const uint4*)(gsrc[j] + k0);
    };
    auto STORES = [&](int s) {
        __nv_bfloat16* st = sm + s * STAGE_E;
#pragma unroll
        for (int j = 0; j < 4; j++)
            *(uint4*)(st + j * BUF_E + soff) = pref[j];
    };
    auto COMPUTE = [&](int s) {
        const uint32_t uAh = smem_u32(sm + s * STAGE_E);
        const uint32_t uAl = uAh + BUF_E * 2;
        const uint32_t uBh = uAl + BUF_E * 2;
        const uint32_t uBl = uBh + BUF_E * 2;
#pragma unroll
        for (int kk = 0; kk < KC; kk += 16) {
            uint32_t ah[2][4], al[2][4];
#pragma unroll
            for (int mt = 0; mt < 2; mt++) {
                const uint32_t offA =
                    ((wm * 32 + mt * 16 + (id & 1) * 8 + r8) * RSTRIDE + kk + (id >> 1) * 8) * 2;
                LDSM4(ah[mt][0], ah[mt][1], ah[mt][2], ah[mt][3], uAh + offA);
                LDSM4(al[mt][0], al[mt][1], al[mt][2], al[mt][3], uAl + offA);
            }
#pragma unroll
            for (int nt2 = 0; nt2 < 2; nt2++) {
                const uint32_t offB =
                    ((wn * 32 + nt2 * 16 + (id >> 1) * 8 + r8) * RSTRIDE + kk + (id & 1) * 8) * 2;
                uint32_t bh[4], bl[4];
                LDSM4(bh[0], bh[1], bh[2], bh[3], uBh + offB);
                LDSM4(bl[0], bl[1], bl[2], bl[3], uBl + offB);
#pragma unroll
                for (int mt = 0; mt < 2; mt++) {
                    MMA_BF16(acc[mt][nt2 * 2],     ah[mt], bh[0], bh[1]);
                    MMA_BF16(acc[mt][nt2 * 2],     ah[mt], bl[0], bl[1]);
                    MMA_BF16(acc[mt][nt2 * 2],     al[mt], bh[0], bh[1]);
                    MMA_BF16(acc[mt][nt2 * 2 + 1], ah[mt], bh[2], bh[3]);
                    MMA_BF16(acc[mt][nt2 * 2 + 1], ah[mt], bl[2], bl[3]);
                    MMA_BF16(acc[mt][nt2 * 2 + 1], al[mt], bh[2], bh[3]);
                }
            }
        }
    };

    LOADG(0);
    STORES(0);
    __syncthreads();

    for (int chunk = 0; chunk < NCHUNK; chunk++) {
        if (chunk + 1 < NCHUNK) LOADG((chunk + 1) * KC);
        COMPUTE(chunk & 1);
        if (chunk + 1 < NCHUNK) STORES((chunk + 1) & 1);
        __syncthreads();
    }

    // ---- epilogue: stage acc in fp32 smem tile (stride 129, conflict-free) ----
    float* ct = (float*)sm;
#pragma unroll
    for (int mt = 0; mt < 2; mt++) {
        const int rl = wm * 32 + mt * 16 + (lane >> 2);
#pragma unroll
        for (int n = 0; n < 4; n++) {
            const int cl = wn * 32 + n * 8 + (lane & 3) * 2;
            ct[rl * 129 + cl]           = acc[mt][n][0];
            ct[rl * 129 + cl + 1]       = acc[mt][n][1];
            ct[(rl + 8) * 129 + cl]     = acc[mt][n][2];
            ct[(rl + 8) * 129 + cl + 1] = acc[mt][n][3];
        }
    }
    __syncthreads();

    const float SCALE = 0.08838834764831845f;
    if (mode <= 1) {
        // tile cols = one full head (HD==128): RoPE pairs (d, d+64) in-tile
        __nv_bfloat16* Oh = mode ? kh : qh;
        __nv_bfloat16* Ol = mode ? kl : ql;
        for (int i = t; i < 128 * 64; i += 512) {
            const int r = i >> 6, d = i & 63;
            const float x0 = ct[r * 129 + d];
            const float x1 = ct[r * 129 + d + 64];
            const float inv_freq = powf(10000.0f, -(float)d * (1.0f / 64.0f));
            const float ang = (float)(m0 + r) * inv_freq;
            const float c = cosf(ang), sn = sinf(ang);
            float r0 = x0 * c - x1 * sn;
            float r1 = x1 * c + x0 * sn;
            if (mode == 0) { r0 *= SCALE; r1 *= SCALE; }
            __nv_bfloat16 h0, l0, h1, l1;
            split_bf16(r0, h0, l0); split_bf16(r1, h1, l1);
            const size_t o = (size_t)(m0 + r) * EMB + n0 + d;
            Oh[o] = h0;      Ol[o] = l0;
            Oh[o + 64] = h1; Ol[o + 64] = l1;
        }
    } else if (mode == 2) {
        for (int i = t; i < 128 * 128; i += 512) {
            const int sl = i & 127, el = i >> 7;
            const float x = ct[sl * 129 + el];
            __nv_bfloat16 h, l;
            split_bf16(x, h, l);
            const size_t o = (size_t)(n0 + el) * SEQ + m0 + sl;
            vth[o] = h; vtl[o] = l;
        }
    } else {
        for (int i = t; i < 128 * 128; i += 512) {
            const int r = i >> 7, c2 = i & 127;
            Cout[(size_t)(m0 + r) * EMB + n0 + c2] = ct[r * 129 + c2];
        }
    }
}

// ---------------- flash attention (R10/R15-proven register-P; bf16 ctx out) ----
#define QSTRIDE 136
#define KSTRIDE 136
#define VSTRIDE 72
#define FQH 0
#define FQL (128 * QSTRIDE)
#define FKV0 (2 * 128 * QSTRIDE)
#define KVSTG (2 * 64 * KSTRIDE + 2 * 128 * VSTRIDE)
#define KH_OFF 0
#define KL_OFF (64 * KSTRIDE)
#define VH_OFF (2 * 64 * KSTRIDE)
#define VL_OFF (VH_OFF + 128 * VSTRIDE)
#define FSMEM_BYTES ((FKV0 + 2 * KVSTG) * 2)

__global__ void __launch_bounds__(256, 1) flash_reg(
    const __nv_bfloat16* __restrict__ qh, const __nv_bfloat16* __restrict__ ql,
    const __nv_bfloat16* __restrict__ kh, const __nv_bfloat16* __restrict__ kl,
    const __nv_bfloat16* __restrict__ vth, const __nv_bfloat16* __restrict__ vtl,
    __nv_bfloat16* __restrict__ ctxh, __nv_bfloat16* __restrict__ ctxl)
{
    extern __shared__ __align__(16) __nv_bfloat16 fs[];
    const uint32_t su = smem_u32(fs);

    const int t    = threadIdx.x;
    const int lane = t & 31;
    const int wid  = t >> 5;
    const int id   = lane >> 3;
    const int r8   = lane & 7;
    const int h    = blockIdx.y;
    const int m0   = blockIdx.x * 128;
    const int hb   = h * HD;

#pragma unroll
    for (int j = 0; j < 8; j++) {
        const int idx = j * 256 + t;
        const int r = idx >> 4;
        const int c = (idx & 15) * 8;
        *(uint4*)(fs + FQH + r * QSTRIDE + c) =
            *(const uint4*)(qh + (size_t)(m0 + r) * EMB + hb + c);
        *(uint4*)(fs + FQL + r * QSTRIDE + c) =
            *(const uint4*)(ql + (size_t)(m0 + r) * EMB + hb + c);
    }

    auto ISSUE_KV = [&](int stage, int n0) {
        const uint32_t sb = su + (uint32_t)(FKV0 + stage * KVSTG) * 2;
#pragma unroll
        for (int j = 0; j < 8; j++) {
            const int c = j * 256 + t;
            const int buf = c >> 10;
            const int cc = c & 1023;
            const int row = cc >> 4;
            const int col = (cc & 15) * 8;
            const __nv_bfloat16* src =
                (buf ? kl : kh) + (size_t)(n0 + row) * EMB + hb + col;
            CP16(sb + (uint32_t)(buf ? KL_OFF : KH_OFF) * 2 +
                 (uint32_t)(row * KSTRIDE + col) * 2, src);
        }
#pragma unroll
        for (int j = 0; j < 8; j++) {
            const int c = j * 256 + t;
            const int buf = c >> 10;
            const int cc = c & 1023;
            const int row = cc >> 3;
            const int col = (cc & 7) * 8;
            const __nv_bfloat16* src =
                (buf ? vtl : vth) + (size_t)(hb + row) * SEQ + n0 + col;
            CP16(sb + (uint32_t)(buf ? VL_OFF : VH_OFF) * 2 +
                 (uint32_t)(row * VSTRIDE + col) * 2, src);
        }
        CP_COMMIT();
    };

    float acc_o[16][4];
#pragma unroll
    for (int j = 0; j < 16; j++)
#pragma unroll
        for (int c = 0; c < 4; c++) acc_o[j][c] = 0.0f;
    float m_r[2] = {-1.0e30f, -1.0e30f};
    float l_r[2] = {0.0f, 0.0f};

    ISSUE_KV(0, 0);

    for (int kb = 0; kb < SEQ / 64; kb++) {
        if (kb + 1 < SEQ / 64) { ISSUE_KV((kb + 1) & 1, (kb + 1) * 64); CP_WAIT(1); }
        else                   { CP_WAIT(0); }
        __syncthreads();

        const uint32_t sb = su + (uint32_t)(FKV0 + (kb & 1) * KVSTG) * 2;
        const uint32_t uKH = sb + (uint32_t)KH_OFF * 2;
        const uint32_t uKL = sb + (uint32_t)KL_OFF * 2;
        const uint32_t uVH = sb + (uint32_t)VH_OFF * 2;
        const uint32_t uVL = sb + (uint32_t)VL_OFF * 2;

        float acc_s[8][4];
#pragma unroll
        for (int j = 0; j < 8; j++)
#pragma unroll
            for (int c = 0; c < 4; c++) acc_s[j][c] = 0.0f;

#pragma unroll
        for (int kk = 0; kk < 128; kk += 16) {
            const uint32_t offA =
                ((wid * 16 + (id & 1) * 8 + r8) * QSTRIDE + kk + (id >> 1) * 8) * 2;
            uint32_t ah[4], al[4];
            LDSM4(ah[0], ah[1], ah[2], ah[3], su + FQH * 2 + offA);
            LDSM4(al[0], al[1], al[2], al[3], su + FQL * 2 + offA);
#pragma unroll
            for (int nt2 = 0; nt2 < 4; nt2++) {
                const uint32_t offB =
                    ((nt2 * 16 + (id >> 1) * 8 + r8) * KSTRIDE + kk + (id & 1) * 8) * 2;
                uint32_t bh[4], bl[4];
                LDSM4(bh[0], bh[1], bh[2], bh[3], uKH + offB);
                LDSM4(bl[0], bl[1], bl[2], bl[3], uKL + offB);
                MMA_BF16(acc_s[nt2 * 2],     ah, bh[0], bh[1]);
                MMA_BF16(acc_s[nt2 * 2],     ah, bl[0], bl[1]);
                MMA_BF16(acc_s[nt2 * 2],     al, bh[0], bh[1]);
                MMA_BF16(acc_s[nt2 * 2 + 1], ah, bh[2], bh[3]);
                MMA_BF16(acc_s[nt2 * 2 + 1], ah, bl[2], bl[3]);
                MMA_BF16(acc_s[nt2 * 2 + 1], al, bh[2], bh[3]);
            }
        }

#pragma unroll
        for (int hf = 0; hf < 2; hf++) {
            float mx = -1.0e30f;
#pragma unroll
            for (int nt = 0; nt < 8; nt++)
                mx = fmaxf(mx, fmaxf(acc_s[nt][hf * 2], acc_s[nt][hf * 2 + 1]));
            mx = fmaxf(mx, __shfl_xor_sync(0xffffffffu, mx, 1));
            mx = fmaxf(mx, __shfl_xor_sync(0xffffffffu, mx, 2));
            const float mn = fmaxf(m_r[hf], mx);
            const float corr = __expf(m_r[hf] - mn);
            m_r[hf] = mn;
            float ps = 0.0f;
#pragma unroll
            for (int nt = 0; nt < 8; nt++) {
                float p0 = __expf(acc_s[nt][hf * 2]     - mn);
                float p1 = __expf(acc_s[nt][hf * 2 + 1] - mn);
                acc_s[nt][hf * 2]     = p0;
                acc_s[nt][hf * 2 + 1] = p1;
                ps += p0 + p1;
            }
            ps += __shfl_xor_sync(0xffffffffu, ps, 1);
            ps += __shfl_xor_sync(0xffffffffu, ps, 2);
            l_r[hf] = l_r[hf] * corr + ps;
#pragma unroll
            for (int nt = 0; nt < 16; nt++) {
                acc_o[nt][hf * 2]     *= corr;
                acc_o[nt][hf * 2 + 1] *= corr;
            }
        }

        uint32_t pa[4][4], pl[4][4];
#pragma unroll
        for (int k2 = 0; k2 < 4; k2++) {
#pragma unroll
            for (int half = 0; half < 2; half++) {
                const int nt = k2 * 2 + half;
#pragma unroll
                for (int rr = 0; rr < 2; rr++) {
                    __nv_bfloat16 h0, l0, h1, l1;
                    split_bf16(acc_s[nt][rr * 2],     h0, l0);
                    split_bf16(acc_s[nt][rr * 2 + 1], h1, l1);
                    pa[k2][half * 2 + rr] = pack_bf2(h0, h1);
                    pl[k2][half * 2 + rr] = pack_bf2(l0, l1);
                }
            }
        }

#pragma unroll
        for (int k2 = 0; k2 < 4; k2++) {
#pragma unroll
            for (int nt2 = 0; nt2 < 8; nt2++) {
                const uint32_t offB =
                    ((nt2 * 16 + (id >> 1) * 8 + r8) * VSTRIDE + k2 * 16 + (id & 1) * 8) * 2;
                uint32_t bh[4], bl[4];
                LDSM4(bh[0], bh[1], bh[2], bh[3], uVH + offB);
                LDSM4(bl[0], bl[1], bl[2], bl[3], uVL + offB);
                MMA_BF16(acc_o[nt2 * 2],     pa[k2], bh[0], bh[1]);
                MMA_BF16(acc_o[nt2 * 2],     pa[k2], bl[0], bl[1]);
                MMA_BF16(acc_o[nt2 * 2],     pl[k2], bh[0], bh[1]);
                MMA_BF16(acc_o[nt2 * 2 + 1], pa[k2], bh[2], bh[3]);
                MMA_BF16(acc_o[nt2 * 2 + 1], pa[k2], bl[2], bl[3]);
                MMA_BF16(acc_o[nt2 * 2 + 1], pl[k2], bh[2], bh[3]);
            }
        }
        __syncthreads();
    }

    // epilogue: normalize, split hi/lo, write bf16 ctx
#pragma unroll
    for (int hf = 0; hf < 2; hf++) {
        const float inv = 1.0f / l_r[hf];
        const int row = m0 + wid * 16 + hf * 8 + (lane >> 2);
#pragma unroll
        for (int nt = 0; nt < 16; nt++) {
            const int col = hb + nt * 8 + (lane & 3) * 2;
            const float a0 = acc_o[nt][hf * 2] * inv;
            const float a1 = acc_o[nt][hf * 2 + 1] * inv;
            __nv_bfloat16 h0, l0, h1, l1;
            split_bf16(a0, h0, l0); split_bf16(a1, h1, l1);
            *(uint32_t*)(ctxh + (size_t)row * EMB + col) = pack_bf2(h0, h1);
            *(uint32_t*)(ctxl + (size_t)row * EMB + col) = pack_bf2(l0, l1);
        }
    }
}

// ---------------- launch ----------------
extern "C" void kernel_launch(void* const* d_in, const int* in_sizes, int n_in,
                              void* d_out, int out_size)
{
    const float* hs = (const float*)d_in[0];
    const float* Wq = (const float*)d_in[1];
    const float* Wk = (const float*)d_in[2];
    const float* Wv = (const float*)d_in[3];
    const float* Wo = (const float*)d_in[4];
    float* out = (float*)d_out;

    __nv_bfloat16 *hsh, *hsl, *wqh, *wql, *wkh, *wkl, *wvh, *wvl, *woh, *wol;
    __nv_bfloat16 *qh, *ql, *kh, *kl, *vth, *vtl, *ctxh, *ctxl;
    cudaGetSymbolAddress((void**)&hsh, g_hsh);   cudaGetSymbolAddress((void**)&hsl, g_hsl);
    cudaGetSymbolAddress((void**)&wqh, g_wqh);   cudaGetSymbolAddress((void**)&wql, g_wql);
    cudaGetSymbolAddress((void**)&wkh, g_wkh);   cudaGetSymbolAddress((void**)&wkl, g_wkl);
    cudaGetSymbolAddress((void**)&wvh, g_wvh);   cudaGetSymbolAddress((void**)&wvl, g_wvl);
    cudaGetSymbolAddress((void**)&woh, g_woh);   cudaGetSymbolAddress((void**)&wol, g_wol);
    cudaGetSymbolAddress((void**)&qh,  g_qh);    cudaGetSymbolAddress((void**)&ql,  g_ql);
    cudaGetSymbolAddress((void**)&kh,  g_kh);    cudaGetSymbolAddress((void**)&kl,  g_kl);
    cudaGetSymbolAddress((void**)&vth, g_vth);   cudaGetSymbolAddress((void**)&vtl, g_vtl);
    cudaGetSymbolAddress((void**)&ctxh, g_ctxh); cudaGetSymbolAddress((void**)&ctxl, g_ctxl);

    cudaFuncSetAttribute(gemm_fused, cudaFuncAttributeMaxDynamicSharedMemorySize, GSM_BYTES);
    cudaFuncSetAttribute(flash_reg,  cudaFuncAttributeMaxDynamicSharedMemorySize, FSMEM_BYTES);

    // pre-split inputs (fp32 -> bf16 hi/lo)
    split_one<<<4096, 256>>>((const float4*)hs, (uint2*)hsh, (uint2*)hsl);
    split_one<<<4096, 256>>>((const float4*)Wq, (uint2*)wqh, (uint2*)wql);
    split_one<<<4096, 256>>>((const float4*)Wk, (uint2*)wkh, (uint2*)wkl);
    split_one<<<4096, 256>>>((const float4*)Wv, (uint2*)wvh, (uint2*)wvl);
    split_one<<<4096, 256>>>((const float4*)Wo, (uint2*)woh, (uint2*)wol);

    // QKV projections with fused RoPE/scale/transpose epilogues
    gemm_fused<<<dim3(EMB / 128, SEQ / 128, 3), 512, GSM_BYTES>>>(
        hsh, hsl, wqh, wql, wkh, wkl, wvh, wvl,
        qh, ql, kh, kl, vth, vtl, out, -1);

    flash_reg<<<dim3(SEQ / 128, NH), 256, FSMEM_BYTES>>>(
        qh, ql, kh, kl, vth, vtl, ctxh, ctxl);

    // output projection (mode 3 -> fp32 out)
    gemm_fused<<<dim3(EMB / 128, SEQ / 128, 1), 512, GSM_BYTES>>>(
        ctxh, ctxl, woh, wol, woh, wol, woh, wol,
        qh, ql, kh, kl, vth, vtl, out, 3);
}

// round 17
// speedup vs baseline: 1.1476x; 1.1476x over previous
#include <cuda_runtime.h>
#include <cuda_bf16.h>
#include <cstdint>
#include <math.h>

#define SEQ  2048
#define EMB  2048
#define NH   16
#define HD   128

// ---------------- scratch (allocation-free: static device globals) ----------------
__device__ float g_q[(size_t)SEQ * EMB];
__device__ float g_k[(size_t)SEQ * EMB];
__device__ float g_v[(size_t)SEQ * EMB];
__device__ __nv_bfloat16 g_hsh[(size_t)SEQ * EMB];
__device__ __nv_bfloat16 g_hsl[(size_t)SEQ * EMB];
__device__ __nv_bfloat16 g_wqh[(size_t)EMB * EMB];
__device__ __nv_bfloat16 g_wql[(size_t)EMB * EMB];
__device__ __nv_bfloat16 g_wkh[(size_t)EMB * EMB];
__device__ __nv_bfloat16 g_wkl[(size_t)EMB * EMB];
__device__ __nv_bfloat16 g_wvh[(size_t)EMB * EMB];
__device__ __nv_bfloat16 g_wvl[(size_t)EMB * EMB];
__device__ __nv_bfloat16 g_woh[(size_t)EMB * EMB];
__device__ __nv_bfloat16 g_wol[(size_t)EMB * EMB];
__device__ __nv_bfloat16 g_qh[(size_t)SEQ * EMB];
__device__ __nv_bfloat16 g_ql[(size_t)SEQ * EMB];
__device__ __nv_bfloat16 g_kh[(size_t)SEQ * EMB];
__device__ __nv_bfloat16 g_kl[(size_t)SEQ * EMB];
__device__ __nv_bfloat16 g_vth[(size_t)EMB * SEQ];
__device__ __nv_bfloat16 g_vtl[(size_t)EMB * SEQ];
__device__ __nv_bfloat16 g_ctxh[(size_t)SEQ * EMB];
__device__ __nv_bfloat16 g_ctxl[(size_t)SEQ * EMB];

// ======================= helpers ==============
__device__ __forceinline__ uint32_t smem_u32(const void* p) {
    uint32_t a;
    asm("{ .reg .u64 t; cvta.to.shared.u64 t, %1; cvt.u32.u64 %0, t; }" : "=r"(a) : "l"(p));
    return a;
}
#define LDSM4(r0, r1, r2, r3, addr)                                               \
    asm volatile("ldmatrix.sync.aligned.m8n8.x4.shared.b16 {%0,%1,%2,%3}, [%4];"  \
        : "=r"(r0), "=r"(r1), "=r"(r2), "=r"(r3) : "r"(addr))
#define MMA_BF16(c, a, b0, b1)                                                    \
    asm volatile("mma.sync.aligned.m16n8k16.row.col.f32.bf16.bf16.f32 "           \
        "{%0,%1,%2,%3}, {%4,%5,%6,%7}, {%8,%9}, {%0,%1,%2,%3};"                   \
        : "+f"((c)[0]), "+f"((c)[1]), "+f"((c)[2]), "+f"((c)[3])                  \
        : "r"((a)[0]), "r"((a)[1]), "r"((a)[2]), "r"((a)[3]), "r"(b0), "r"(b1))
#define CP16(dst, src) \
    asm volatile("cp.async.cg.shared.global [%0], [%1], 16;" :: "r"(dst), "l"(src))
#define CP_COMMIT() asm volatile("cp.async.commit_group;")
#define CP_WAIT(n)  asm volatile("cp.async.wait_group %0;" :: "n"(n))

__device__ __forceinline__ void split_bf16(float x, __nv_bfloat16& h, __nv_bfloat16& l) {
    h = __float2bfloat16(x);
    l = __float2bfloat16(x - __bfloat162float(h));
}
__device__ __forceinline__ uint32_t pack_bf2(__nv_bfloat16 a, __nv_bfloat16 b) {
    __nv_bfloat162 p = __halves2bfloat162(a, b);
    return *(uint32_t*)&p;
}

// ---------------- batched input split: fp32 -> bf16 hi/lo (5 tensors) ----------
__global__ void __launch_bounds__(256) split_all(
    const float4* __restrict__ s0, const float4* __restrict__ s1,
    const float4* __restrict__ s2, const float4* __restrict__ s3,
    const float4* __restrict__ s4,
    uint2* __restrict__ dh0, uint2* __restrict__ dl0,
    uint2* __restrict__ dh1, uint2* __restrict__ dl1,
    uint2* __restrict__ dh2, uint2* __restrict__ dl2,
    uint2* __restrict__ dh3, uint2* __restrict__ dl3,
    uint2* __restrict__ dh4, uint2* __restrict__ dl4)
{
    const int which = blockIdx.y;
    const float4* src = (which == 0) ? s0 : (which == 1) ? s1 :
                        (which == 2) ? s2 : (which == 3) ? s3 : s4;
    uint2* dh = (which == 0) ? dh0 : (which == 1) ? dh1 :
                (which == 2) ? dh2 : (which == 3) ? dh3 : dh4;
    uint2* dl = (which == 0) ? dl0 : (which == 1) ? dl1 :
                (which == 2) ? dl2 : (which == 3) ? dl3 : dl4;

    const int i = blockIdx.x * 256 + threadIdx.x;   // 1048576 float4 per tensor
    float4 x = src[i];
    __nv_bfloat16 h0, h1, h2, h3, l0, l1, l2, l3;
    split_bf16(x.x, h0, l0); split_bf16(x.y, h1, l1);
    split_bf16(x.z, h2, l2); split_bf16(x.w, h3, l3);
    dh[i] = make_uint2(pack_bf2(h0, h1), pack_bf2(h2, h3));
    dl[i] = make_uint2(pack_bf2(l0, l1), pack_bf2(l2, l3));
}

// ============ HMMA NT GEMM (R15-proven): register-prefetch, bf16 inputs ========
// 512 threads, 16 warps, warp tile 32x32, double-buffered smem, no hot-loop cvt.
#define KC      32
#define NCHUNK  (EMB / KC)
#define RSTRIDE 40
#define BUF_E   (128 * RSTRIDE)
#define STAGE_E (4 * BUF_E)
#define GSM_BYTES (2 * STAGE_E * 2)

__global__ void __launch_bounds__(512, 1) gemm_mma_bf(
    const __nv_bfloat16* __restrict__ Ah_, const __nv_bfloat16* __restrict__ Al_,
    const __nv_bfloat16* __restrict__ Bh0, const __nv_bfloat16* __restrict__ Bl0,
    const __nv_bfloat16* __restrict__ Bh1, const __nv_bfloat16* __restrict__ Bl1,
    const __nv_bfloat16* __restrict__ Bh2, const __nv_bfloat16* __restrict__ Bl2,
    float* __restrict__ C0, float* __restrict__ C1, float* __restrict__ C2)
{
    const __nv_bfloat16* Bh = (blockIdx.z == 0) ? Bh0 : (blockIdx.z == 1) ? Bh1 : Bh2;
    const __nv_bfloat16* Bl = (blockIdx.z == 0) ? Bl0 : (blockIdx.z == 1) ? Bl1 : Bl2;
    float*               C  = (blockIdx.z == 0) ? C0  : (blockIdx.z == 1) ? C1  : C2;

    extern __shared__ __align__(16) __nv_bfloat16 sm[];

    const int t    = threadIdx.x;
    const int lane = t & 31;
    const int wid  = t >> 5;           // 0..15
    const int wm   = wid & 3;          // 32-row band
    const int wn   = wid >> 2;         // 0..3: 32-col band
    const int m0   = blockIdx.y * 128;
    const int n0   = blockIdx.x * 128;
    const int id   = lane >> 3;
    const int r8   = lane & 7;

    float acc[2][4][4];
#pragma unroll
    for (int i = 0; i < 2; i++)
#pragma unroll
        for (int j = 0; j < 4; j++)
#pragma unroll
            for (int c = 0; c < 4; c++) acc[i][j][c] = 0.0f;

    // per-thread load slot: row = t>>2 (0..127), 8-elem group cq = (t&3)*8.
    const int prow = t >> 2;
    const int pcq  = (t & 3) * 8;
    const __nv_bfloat16* gsrc[4] = {
        Ah_ + (size_t)(m0 + prow) * EMB + pcq,
        Al_ + (size_t)(m0 + prow) * EMB + pcq,
        Bh  + (size_t)(n0 + prow) * EMB + pcq,
        Bl  + (size_t)(n0 + prow) * EMB + pcq
    };
    const int soff = prow * RSTRIDE + pcq;

    uint4 pref[4];

    auto LOADG = [&](int k0) {
#pragma unroll
        for (int j = 0; j < 4; j++)
            pref[j] = *(const uint4*)(gsrc[j] + k0);
    };
    auto STORES = [&](int s) {
        __nv_bfloat16* st = sm + s * STAGE_E;
#pragma unroll
        for (int j = 0; j < 4; j++)
            *(uint4*)(st + j * BUF_E + soff) = pref[j];
    };
    auto COMPUTE = [&](int s) {
        const uint32_t uAh = smem_u32(sm + s * STAGE_E);
        const uint32_t uAl = uAh + BUF_E * 2;
        const uint32_t uBh = uAl + BUF_E * 2;
        const uint32_t uBl = uBh + BUF_E * 2;
#pragma unroll
        for (int kk = 0; kk < KC; kk += 16) {
            uint32_t ah[2][4], al[2][4];
#pragma unroll
            for (int mt = 0; mt < 2; mt++) {
                const uint32_t offA =
                    ((wm * 32 + mt * 16 + (id & 1) * 8 + r8) * RSTRIDE + kk + (id >> 1) * 8) * 2;
                LDSM4(ah[mt][0], ah[mt][1], ah[mt][2], ah[mt][3], uAh + offA);
                LDSM4(al[mt][0], al[mt][1], al[mt][2], al[mt][3], uAl + offA);
            }
#pragma unroll
            for (int nt2 = 0; nt2 < 2; nt2++) {
                const uint32_t offB =
                    ((wn * 32 + nt2 * 16 + (id >> 1) * 8 + r8) * RSTRIDE + kk + (id & 1) * 8) * 2;
                uint32_t bh[4], bl[4];
                LDSM4(bh[0], bh[1], bh[2], bh[3], uBh + offB);
                LDSM4(bl[0], bl[1], bl[2], bl[3], uBl + offB);
#pragma unroll
                for (int mt = 0; mt < 2; mt++) {
                    MMA_BF16(acc[mt][nt2 * 2],     ah[mt], bh[0], bh[1]);
                    MMA_BF16(acc[mt][nt2 * 2],     ah[mt], bl[0], bl[1]);
                    MMA_BF16(acc[mt][nt2 * 2],     al[mt], bh[0], bh[1]);
                    MMA_BF16(acc[mt][nt2 * 2 + 1], ah[mt], bh[2], bh[3]);
                    MMA_BF16(acc[mt][nt2 * 2 + 1], ah[mt], bl[2], bl[3]);
                    MMA_BF16(acc[mt][nt2 * 2 + 1], al[mt], bh[2], bh[3]);
                }
            }
        }
    };

    LOADG(0);
    STORES(0);
    __syncthreads();

    for (int chunk = 0; chunk < NCHUNK; chunk++) {
        if (chunk + 1 < NCHUNK) LOADG((chunk + 1) * KC);
        COMPUTE(chunk & 1);
        if (chunk + 1 < NCHUNK) STORES((chunk + 1) & 1);
        __syncthreads();
    }

#pragma unroll
    for (int mt = 0; mt < 2; mt++) {
        const int row = m0 + wm * 32 + mt * 16 + (lane >> 2);
#pragma unroll
        for (int n = 0; n < 4; n++) {
            const int col = n0 + wn * 32 + n * 8 + (lane & 3) * 2;
            *(float2*)(C + (size_t)row * EMB + col) =
                make_float2(acc[mt][n][0], acc[mt][n][1]);
            *(float2*)(C + (size_t)(row + 8) * EMB + col) =
                make_float2(acc[mt][n][2], acc[mt][n][3]);
        }
    }
}

// ---------- RoPE + scale + split-convert (widened blocks: 4 tokens / 256 thr) ----
__global__ void __launch_bounds__(256) rope_convert(
    const float* __restrict__ q, const float* __restrict__ k,
    __nv_bfloat16* __restrict__ qh, __nv_bfloat16* __restrict__ ql,
    __nv_bfloat16* __restrict__ kh, __nv_bfloat16* __restrict__ kl)
{
    const int s = blockIdx.x * 4 + (threadIdx.x >> 6);
    const int i = threadIdx.x & 63;
    const int h = blockIdx.y;
    const float SCALE = 0.08838834764831845f;

    const float inv_freq = powf(10000.0f, -(float)i * (1.0f / 64.0f));
    const float ang = (float)s * inv_freq;
    const float c  = cosf(ang);
    const float sn = sinf(ang);

    const size_t base = (size_t)s * EMB + (size_t)h * HD;

    {
        float x0 = q[base + i], x1 = q[base + i + 64];
        float r0 = (x0 * c - x1 * sn) * SCALE;
        float r1 = (x1 * c + x0 * sn) * SCALE;
        __nv_bfloat16 h0, l0, h1, l1;
        split_bf16(r0, h0, l0); split_bf16(r1, h1, l1);
        qh[base + i] = h0;      ql[base + i] = l0;
        qh[base + i + 64] = h1; ql[base + i + 64] = l1;
    }
    {
        float x0 = k[base + i], x1 = k[base + i + 64];
        float r0 = x0 * c - x1 * sn;
        float r1 = x1 * c + x0 * sn;
        __nv_bfloat16 h0, l0, h1, l1;
        split_bf16(r0, h0, l0); split_bf16(r1, h1, l1);
        kh[base + i] = h0;      kl[base + i] = l0;
        kh[base + i + 64] = h1; kl[base + i + 64] = l1;
    }
}

// ---------- V transpose + split ----------
__global__ void __launch_bounds__(256) vtrans(
    const float* __restrict__ v,
    __nv_bfloat16* __restrict__ vth, __nv_bfloat16* __restrict__ vtl)
{
    __shared__ float tile[32][33];
    const int s0 = blockIdx.x * 32;
    const int e0 = blockIdx.y * 32;
    const int tx = threadIdx.x & 31;
    const int ty = threadIdx.x >> 5;

#pragma unroll
    for (int j = 0; j < 4; j++) {
        const int r = ty + j * 8;
        tile[r][tx] = v[(size_t)(s0 + r) * EMB + e0 + tx];
    }
    __syncthreads();
#pragma unroll
    for (int j = 0; j < 4; j++) {
        const int el = ty + j * 8;
        const float x = tile[tx][el];
        __nv_bfloat16 h, l;
        split_bf16(x, h, l);
        const size_t o = (size_t)(e0 + el) * SEQ + s0 + tx;
        vth[o] = h;
        vtl[o] = l;
    }
}

// ---------------- flash attention (R10/R15-proven register-P; bf16 ctx out) ----
#define QSTRIDE 136
#define KSTRIDE 136
#define VSTRIDE 72
#define FQH 0
#define FQL (128 * QSTRIDE)
#define FKV0 (2 * 128 * QSTRIDE)
#define KVSTG (2 * 64 * KSTRIDE + 2 * 128 * VSTRIDE)
#define KH_OFF 0
#define KL_OFF (64 * KSTRIDE)
#define VH_OFF (2 * 64 * KSTRIDE)
#define VL_OFF (VH_OFF + 128 * VSTRIDE)
#define FSMEM_BYTES ((FKV0 + 2 * KVSTG) * 2)

__global__ void __launch_bounds__(256, 1) flash_reg(
    const __nv_bfloat16* __restrict__ qh, const __nv_bfloat16* __restrict__ ql,
    const __nv_bfloat16* __restrict__ kh, const __nv_bfloat16* __restrict__ kl,
    const __nv_bfloat16* __restrict__ vth, const __nv_bfloat16* __restrict__ vtl,
    __nv_bfloat16* __restrict__ ctxh, __nv_bfloat16* __restrict__ ctxl)
{
    extern __shared__ __align__(16) __nv_bfloat16 fs[];
    const uint32_t su = smem_u32(fs);

    const int t    = threadIdx.x;
    const int lane = t & 31;
    const int wid  = t >> 5;
    const int id   = lane >> 3;
    const int r8   = lane & 7;
    const int h    = blockIdx.y;
    const int m0   = blockIdx.x * 128;
    const int hb   = h * HD;

#pragma unroll
    for (int j = 0; j < 8; j++) {
        const int idx = j * 256 + t;
        const int r = idx >> 4;
        const int c = (idx & 15) * 8;
        *(uint4*)(fs + FQH + r * QSTRIDE + c) =
            *(const uint4*)(qh + (size_t)(m0 + r) * EMB + hb + c);
        *(uint4*)(fs + FQL + r * QSTRIDE + c) =
            *(const uint4*)(ql + (size_t)(m0 + r) * EMB + hb + c);
    }

    auto ISSUE_KV = [&](int stage, int n0) {
        const uint32_t sb = su + (uint32_t)(FKV0 + stage * KVSTG) * 2;
#pragma unroll
        for (int j = 0; j < 8; j++) {
            const int c = j * 256 + t;
            const int buf = c >> 10;
            const int cc = c & 1023;
            const int row = cc >> 4;
            const int col = (cc & 15) * 8;
            const __nv_bfloat16* src =
                (buf ? kl : kh) + (size_t)(n0 + row) * EMB + hb + col;
            CP16(sb + (uint32_t)(buf ? KL_OFF : KH_OFF) * 2 +
                 (uint32_t)(row * KSTRIDE + col) * 2, src);
        }
#pragma unroll
        for (int j = 0; j < 8; j++) {
            const int c = j * 256 + t;
            const int buf = c >> 10;
            const int cc = c & 1023;
            const int row = cc >> 3;
            const int col = (cc & 7) * 8;
            const __nv_bfloat16* src =
                (buf ? vtl : vth) + (size_t)(hb + row) * SEQ + n0 + col;
            CP16(sb + (uint32_t)(buf ? VL_OFF : VH_OFF) * 2 +
                 (uint32_t)(row * VSTRIDE + col) * 2, src);
        }
        CP_COMMIT();
    };

    float acc_o[16][4];
#pragma unroll
    for (int j = 0; j < 16; j++)
#pragma unroll
        for (int c = 0; c < 4; c++) acc_o[j][c] = 0.0f;
    float m_r[2] = {-1.0e30f, -1.0e30f};
    float l_r[2] = {0.0f, 0.0f};

    ISSUE_KV(0, 0);

    for (int kb = 0; kb < SEQ / 64; kb++) {
        if (kb + 1 < SEQ / 64) { ISSUE_KV((kb + 1) & 1, (kb + 1) * 64); CP_WAIT(1); }
        else                   { CP_WAIT(0); }
        __syncthreads();

        const uint32_t sb = su + (uint32_t)(FKV0 + (kb & 1) * KVSTG) * 2;
        const uint32_t uKH = sb + (uint32_t)KH_OFF * 2;
        const uint32_t uKL = sb + (uint32_t)KL_OFF * 2;
        const uint32_t uVH = sb + (uint32_t)VH_OFF * 2;
        const uint32_t uVL = sb + (uint32_t)VL_OFF * 2;

        float acc_s[8][4];
#pragma unroll
        for (int j = 0; j < 8; j++)
#pragma unroll
            for (int c = 0; c < 4; c++) acc_s[j][c] = 0.0f;

#pragma unroll
        for (int kk = 0; kk < 128; kk += 16) {
            const uint32_t offA =
                ((wid * 16 + (id & 1) * 8 + r8) * QSTRIDE + kk + (id >> 1) * 8) * 2;
            uint32_t ah[4], al[4];
            LDSM4(ah[0], ah[1], ah[2], ah[3], su + FQH * 2 + offA);
            LDSM4(al[0], al[1], al[2], al[3], su + FQL * 2 + offA);
#pragma unroll
            for (int nt2 = 0; nt2 < 4; nt2++) {
                const uint32_t offB =
                    ((nt2 * 16 + (id >> 1) * 8 + r8) * KSTRIDE + kk + (id & 1) * 8) * 2;
                uint32_t bh[4], bl[4];
                LDSM4(bh[0], bh[1], bh[2], bh[3], uKH + offB);
                LDSM4(bl[0], bl[1], bl[2], bl[3], uKL + offB);
                MMA_BF16(acc_s[nt2 * 2],     ah, bh[0], bh[1]);
                MMA_BF16(acc_s[nt2 * 2],     ah, bl[0], bl[1]);
                MMA_BF16(acc_s[nt2 * 2],     al, bh[0], bh[1]);
                MMA_BF16(acc_s[nt2 * 2 + 1], ah, bh[2], bh[3]);
                MMA_BF16(acc_s[nt2 * 2 + 1], ah, bl[2], bl[3]);
                MMA_BF16(acc_s[nt2 * 2 + 1], al, bh[2], bh[3]);
            }
        }

#pragma unroll
        for (int hf = 0; hf < 2; hf++) {
            float mx = -1.0e30f;
#pragma unroll
            for (int nt = 0; nt < 8; nt++)
                mx = fmaxf(mx, fmaxf(acc_s[nt][hf * 2], acc_s[nt][hf * 2 + 1]));
            mx = fmaxf(mx, __shfl_xor_sync(0xffffffffu, mx, 1));
            mx = fmaxf(mx, __shfl_xor_sync(0xffffffffu, mx, 2));
            const float mn = fmaxf(m_r[hf], mx);
            const float corr = __expf(m_r[hf] - mn);
            m_r[hf] = mn;
            float ps = 0.0f;
#pragma unroll
            for (int nt = 0; nt < 8; nt++) {
                float p0 = __expf(acc_s[nt][hf * 2]     - mn);
                float p1 = __expf(acc_s[nt][hf * 2 + 1] - mn);
                acc_s[nt][hf * 2]     = p0;
                acc_s[nt][hf * 2 + 1] = p1;
                ps += p0 + p1;
            }
            ps += __shfl_xor_sync(0xffffffffu, ps, 1);
            ps += __shfl_xor_sync(0xffffffffu, ps, 2);
            l_r[hf] = l_r[hf] * corr + ps;
#pragma unroll
            for (int nt = 0; nt < 16; nt++) {
                acc_o[nt][hf * 2]     *= corr;
                acc_o[nt][hf * 2 + 1] *= corr;
            }
        }

        uint32_t pa[4][4], pl[4][4];
#pragma unroll
        for (int k2 = 0; k2 < 4; k2++) {
#pragma unroll
            for (int half = 0; half < 2; half++) {
                const int nt = k2 * 2 + half;
#pragma unroll
                for (int rr = 0; rr < 2; rr++) {
                    __nv_bfloat16 h0, l0, h1, l1;
                    split_bf16(acc_s[nt][rr * 2],     h0, l0);
                    split_bf16(acc_s[nt][rr * 2 + 1], h1, l1);
                    pa[k2][half * 2 + rr] = pack_bf2(h0, h1);
                    pl[k2][half * 2 + rr] = pack_bf2(l0, l1);
                }
            }
        }

#pragma unroll
        for (int k2 = 0; k2 < 4; k2++) {
#pragma unroll
            for (int nt2 = 0; nt2 < 8; nt2++) {
                const uint32_t offB =
                    ((nt2 * 16 + (id >> 1) * 8 + r8) * VSTRIDE + k2 * 16 + (id & 1) * 8) * 2;
                uint32_t bh[4], bl[4];
                LDSM4(bh[0], bh[1], bh[2], bh[3], uVH + offB);
                LDSM4(bl[0], bl[1], bl[2], bl[3], uVL + offB);
                MMA_BF16(acc_o[nt2 * 2],     pa[k2], bh[0], bh[1]);
                MMA_BF16(acc_o[nt2 * 2],     pa[k2], bl[0], bl[1]);
                MMA_BF16(acc_o[nt2 * 2],     pl[k2], bh[0], bh[1]);
                MMA_BF16(acc_o[nt2 * 2 + 1], pa[k2], bh[2], bh[3]);
                MMA_BF16(acc_o[nt2 * 2 + 1], pa[k2], bl[2], bl[3]);
                MMA_BF16(acc_o[nt2 * 2 + 1], pl[k2], bh[2], bh[3]);
            }
        }
        __syncthreads();
    }

    // epilogue: normalize, split hi/lo, write bf16 ctx
#pragma unroll
    for (int hf = 0; hf < 2; hf++) {
        const float inv = 1.0f / l_r[hf];
        const int row = m0 + wid * 16 + hf * 8 + (lane >> 2);
#pragma unroll
        for (int nt = 0; nt < 16; nt++) {
            const int col = hb + nt * 8 + (lane & 3) * 2;
            const float a0 = acc_o[nt][hf * 2] * inv;
            const float a1 = acc_o[nt][hf * 2 + 1] * inv;
            __nv_bfloat16 h0, l0, h1, l1;
            split_bf16(a0, h0, l0); split_bf16(a1, h1, l1);
            *(uint32_t*)(ctxh + (size_t)row * EMB + col) = pack_bf2(h0, h1);
            *(uint32_t*)(ctxl + (size_t)row * EMB + col) = pack_bf2(l0, l1);
        }
    }
}

// ---------------- launch ----------------
extern "C" void kernel_launch(void* const* d_in, const int* in_sizes, int n_in,
                              void* d_out, int out_size)
{
    const float* hs = (const float*)d_in[0];
    const float* Wq = (const float*)d_in[1];
    const float* Wk = (const float*)d_in[2];
    const float* Wv = (const float*)d_in[3];
    const float* Wo = (const float*)d_in[4];
    float* out = (float*)d_out;

    float *q, *k, *v;
    __nv_bfloat16 *hsh, *hsl, *wqh, *wql, *wkh, *wkl, *wvh, *wvl, *woh, *wol;
    __nv_bfloat16 *qh, *ql, *kh, *kl, *vth, *vtl, *ctxh, *ctxl;
    cudaGetSymbolAddress((void**)&q,   g_q);
    cudaGetSymbolAddress((void**)&k,   g_k);
    cudaGetSymbolAddress((void**)&v,   g_v);
    cudaGetSymbolAddress((void**)&hsh, g_hsh);   cudaGetSymbolAddress((void**)&hsl, g_hsl);
    cudaGetSymbolAddress((void**)&wqh, g_wqh);   cudaGetSymbolAddress((void**)&wql, g_wql);
    cudaGetSymbolAddress((void**)&wkh, g_wkh);   cudaGetSymbolAddress((void**)&wkl, g_wkl);
    cudaGetSymbolAddress((void**)&wvh, g_wvh);   cudaGetSymbolAddress((void**)&wvl, g_wvl);
    cudaGetSymbolAddress((void**)&woh, g_woh);   cudaGetSymbolAddress((void**)&wol, g_wol);
    cudaGetSymbolAddress((void**)&qh,  g_qh);    cudaGetSymbolAddress((void**)&ql,  g_ql);
    cudaGetSymbolAddress((void**)&kh,  g_kh);    cudaGetSymbolAddress((void**)&kl,  g_kl);
    cudaGetSymbolAddress((void**)&vth, g_vth);   cudaGetSymbolAddress((void**)&vtl, g_vtl);
    cudaGetSymbolAddress((void**)&ctxh, g_ctxh); cudaGetSymbolAddress((void**)&ctxl, g_ctxl);

    cudaFuncSetAttribute(gemm_mma_bf, cudaFuncAttributeMaxDynamicSharedMemorySize, GSM_BYTES);
    cudaFuncSetAttribute(flash_reg,   cudaFuncAttributeMaxDynamicSharedMemorySize, FSMEM_BYTES);

    // batched pre-split of all 5 fp32 inputs -> bf16 hi/lo
    split_all<<<dim3(4096, 5), 256>>>(
        (const float4*)hs, (const float4*)Wq, (const float4*)Wk,
        (const float4*)Wv, (const float4*)Wo,
        (uint2*)hsh, (uint2*)hsl, (uint2*)wqh, (uint2*)wql,
        (uint2*)wkh, (uint2*)wkl, (uint2*)wvh, (uint2*)wvl,
        (uint2*)woh, (uint2*)wol);

    // QKV projections (fp32 q,k,v out for rope/vtrans)
    gemm_mma_bf<<<dim3(EMB / 128, SEQ / 128, 3), 512, GSM_BYTES>>>(
        hsh, hsl, wqh, wql, wkh, wkl, wvh, wvl, q, k, v);

    rope_convert<<<dim3(SEQ / 4, NH), 256>>>(q, k, qh, ql, kh, kl);
    vtrans<<<dim3(SEQ / 32, EMB / 32), 256>>>(v, vth, vtl);

    flash_reg<<<dim3(SEQ / 128, NH), 256, FSMEM_BYTES>>>(
        qh, ql, kh, kl, vth, vtl, ctxh, ctxl);

    // output projection (ctx pre-split by flash epilogue)
    gemm_mma_bf<<<dim3(EMB / 128, SEQ / 128, 1), 512, GSM_BYTES>>>(
        ctxh, ctxl, woh, wol, woh, wol, woh, wol, out, out, out);
}